// round 1
// baseline (speedup 1.0000x reference)
#include <cuda_runtime.h>
#include <math.h>

#define N_NODES 100000
#define N_EDGES 1200000
#define HID 64
#define NB_SCAN 98   // ceil(100000/1024)

// ---------------- scratch (device globals, no allocation) ----------------
__device__ float g_H[(size_t)N_NODES * HID];   // GEMM output (layer1 and layer2)
__device__ float g_Z[(size_t)N_NODES * HID];   // post-SELU activations
__device__ int   g_rowptr[N_NODES + 1];
__device__ int   g_perm[N_EDGES];
__device__ int   g_cnt[N_NODES];
__device__ int   g_bsums[NB_SCAN + 1];

// ---------------- CSR build ----------------
__global__ void zero_cnt_kernel() {
    int i = blockIdx.x * 256 + threadIdx.x;
    if (i < N_NODES) g_cnt[i] = 0;
}

__global__ void edge_count_kernel(const int* __restrict__ rows) {
    int e = blockIdx.x * 256 + threadIdx.x;
    if (e < N_EDGES) atomicAdd(&g_cnt[rows[e]], 1);
}

__global__ void scan_reduce_kernel() {
    __shared__ int s[256];
    int t = threadIdx.x;
    int base = blockIdx.x * 1024 + t * 4;
    int v = 0;
#pragma unroll
    for (int i = 0; i < 4; i++) {
        int idx = base + i;
        if (idx < N_NODES) v += g_cnt[idx];
    }
    s[t] = v;
    __syncthreads();
    for (int o = 128; o; o >>= 1) {
        if (t < o) s[t] += s[t + o];
        __syncthreads();
    }
    if (t == 0) g_bsums[blockIdx.x] = s[0];
}

__global__ void scan_bsums_kernel() {
    __shared__ int s[2][128];
    int t = threadIdx.x;
    int v = (t < NB_SCAN) ? g_bsums[t] : 0;
    int buf = 0;
    s[0][t] = v;
    __syncthreads();
    for (int o = 1; o < 128; o <<= 1) {
        int x = s[buf][t];
        if (t >= o) x += s[buf][t - o];
        s[buf ^ 1][t] = x;
        buf ^= 1;
        __syncthreads();
    }
    int inc = s[buf][t];
    if (t < NB_SCAN) g_bsums[t] = inc - v;   // exclusive
    if (t == 127) g_bsums[NB_SCAN] = inc;    // total
}

__global__ void scan_final_kernel() {
    __shared__ int s[2][256];
    int t = threadIdx.x;
    int base = blockIdx.x * 1024 + t * 4;
    int v[4];
#pragma unroll
    for (int i = 0; i < 4; i++)
        v[i] = (base + i < N_NODES) ? g_cnt[base + i] : 0;
    int tot = v[0] + v[1] + v[2] + v[3];
    int buf = 0;
    s[0][t] = tot;
    __syncthreads();
    for (int o = 1; o < 256; o <<= 1) {
        int x = s[buf][t];
        if (t >= o) x += s[buf][t - o];
        s[buf ^ 1][t] = x;
        buf ^= 1;
        __syncthreads();
    }
    int run = s[buf][t] - tot + g_bsums[blockIdx.x];   // exclusive prefix + block offset
#pragma unroll
    for (int i = 0; i < 4; i++) {
        if (base + i < N_NODES) g_rowptr[base + i] = run;
        run += v[i];
    }
    if (blockIdx.x == 0 && t == 0) g_rowptr[N_NODES] = g_bsums[NB_SCAN];
}

__global__ void edge_scatter_kernel(const int* __restrict__ rows) {
    int e = blockIdx.x * 256 + threadIdx.x;
    if (e < N_EDGES) {
        int r = rows[e];
        int p = g_rowptr[r] + atomicAdd(&g_cnt[r], 1);
        g_perm[p] = e;
    }
}

// ---------------- GEMM: g_H = A[M x K] @ B[K x 64] ----------------
// BM=64, BN=64, BK=16, 256 threads, 4x4 register tile per thread.
__global__ __launch_bounds__(256) void gemm64_kernel(const float* __restrict__ A_ext,
                                                     int use_gz,
                                                     const float* __restrict__ B,
                                                     int K) {
    const float* __restrict__ A = use_gz ? g_Z : A_ext;
    __shared__ float As[16][68];   // transposed tile, padded for conflicts + float4 alignment
    __shared__ float Bs[16][64];
    int tid = threadIdx.x;
    int tx = tid & 15, ty = tid >> 4;
    int row0 = blockIdx.x * 64;

    float acc[4][4];
#pragma unroll
    for (int i = 0; i < 4; i++)
#pragma unroll
        for (int j = 0; j < 4; j++) acc[i][j] = 0.f;

    for (int k0 = 0; k0 < K; k0 += 16) {
#pragma unroll
        for (int i = 0; i < 4; i++) {
            int idx = tid + i * 256;
            int m = idx >> 4, kk = idx & 15;
            int gr = row0 + m;
            As[kk][m] = (gr < N_NODES) ? __ldg(&A[(size_t)gr * K + k0 + kk]) : 0.f;
        }
#pragma unroll
        for (int i = 0; i < 4; i++) {
            int idx = tid + i * 256;
            int kk = idx >> 6, n = idx & 63;
            Bs[kk][n] = __ldg(&B[(k0 + kk) * 64 + n]);
        }
        __syncthreads();
#pragma unroll
        for (int kk = 0; kk < 16; kk++) {
            float4 a4 = *(const float4*)&As[kk][ty * 4];
            float4 b4 = *(const float4*)&Bs[kk][tx * 4];
            float av[4] = {a4.x, a4.y, a4.z, a4.w};
            float bv[4] = {b4.x, b4.y, b4.z, b4.w};
#pragma unroll
            for (int i = 0; i < 4; i++)
#pragma unroll
                for (int j = 0; j < 4; j++) acc[i][j] += av[i] * bv[j];
        }
        __syncthreads();
    }
#pragma unroll
    for (int i = 0; i < 4; i++) {
        int row = row0 + ty * 4 + i;
        if (row < N_NODES) {
            float4 v = make_float4(acc[i][0], acc[i][1], acc[i][2], acc[i][3]);
            *(float4*)&g_H[(size_t)row * 64 + tx * 4] = v;
        }
    }
}

// ---------------- SPMM (CSR gather) + fused epilogue ----------------
__device__ __forceinline__ float warp_sum(float v) {
#pragma unroll
    for (int o = 16; o; o >>= 1) v += __shfl_xor_sync(0xffffffffu, v, o);
    return v;
}

// MODE 0: out = SELU(A@H + b) -> g_Z ; MODE 1: out = rownorm(A@H + b) -> out_ext
template <int MODE>
__global__ __launch_bounds__(256) void spmm_kernel(const int* __restrict__ cols,
                                                   const float* __restrict__ vals,
                                                   const float* __restrict__ bias,
                                                   float* __restrict__ out_ext) {
    int warp = threadIdx.x >> 5, lane = threadIdx.x & 31;
    int row = blockIdx.x * 8 + warp;
    if (row >= N_NODES) return;
    int s = g_rowptr[row], e = g_rowptr[row + 1];
    float ax = 0.f, ay = 0.f;
    for (int j = s; j < e; j++) {
        int ed = __ldg(&g_perm[j]);
        int c = __ldg(&cols[ed]);
        float v = __ldg(&vals[ed]);
        float2 h = *(const float2*)&g_H[(size_t)c * 64 + lane * 2];
        ax += v * h.x;
        ay += v * h.y;
    }
    ax += __ldg(&bias[lane * 2]);
    ay += __ldg(&bias[lane * 2 + 1]);
    if (MODE == 0) {
        const float sc = 1.0507009873554805f, al = 1.6732632423543772f;
        ax = ax > 0.f ? sc * ax : sc * al * expm1f(ax);
        ay = ay > 0.f ? sc * ay : sc * al * expm1f(ay);
        float2 o = {ax, ay};
        *(float2*)&g_Z[(size_t)row * 64 + lane * 2] = o;
    } else {
        float ss = warp_sum(ax * ax + ay * ay);
        float inv = 1.f / fmaxf(sqrtf(ss), 1e-12f);
        float2 o = {ax * inv, ay * inv};
        *(float2*)&out_ext[(size_t)row * 64 + lane * 2] = o;
    }
}

// ---------------- launch ----------------
extern "C" void kernel_launch(void* const* d_in, const int* in_sizes, int n_in,
                              void* d_out, int out_size) {
    const float* X[2]    = {(const float*)d_in[0], (const float*)d_in[1]};
    const int*   rows[2] = {(const int*)d_in[2], (const int*)d_in[5]};
    const int*   cols[2] = {(const int*)d_in[3], (const int*)d_in[6]};
    const float* vals[2] = {(const float*)d_in[4], (const float*)d_in[7]};
    const float* W1 = (const float*)d_in[8];
    const float* b1 = (const float*)d_in[9];
    const float* W2 = (const float*)d_in[10];
    const float* b2 = (const float*)d_in[11];
    float* out = (float*)d_out;

    const int ZG = (N_NODES + 255) / 256;   // 391
    const int EG = (N_EDGES + 255) / 256;   // 4688
    const int GG = (N_NODES + 63) / 64;     // 1563
    const int SG = (N_NODES + 7) / 8;       // 12500

    for (int g = 0; g < 2; g++) {
        // CSR build for graph g
        zero_cnt_kernel<<<ZG, 256>>>();
        edge_count_kernel<<<EG, 256>>>(rows[g]);
        scan_reduce_kernel<<<NB_SCAN, 256>>>();
        scan_bsums_kernel<<<1, 128>>>();
        scan_final_kernel<<<NB_SCAN, 256>>>();
        zero_cnt_kernel<<<ZG, 256>>>();
        edge_scatter_kernel<<<EG, 256>>>(rows[g]);

        // layer 1: H = X @ W1 ; Z = SELU(A@H + b1)
        gemm64_kernel<<<GG, 256>>>(X[g], 0, W1, 256);
        spmm_kernel<0><<<SG, 256>>>(cols[g], vals[g], b1, nullptr);

        // layer 2: H = Z @ W2 ; out = rownorm(A@H + b2)
        gemm64_kernel<<<GG, 256>>>(nullptr, 1, W2, HID);
        spmm_kernel<1><<<SG, 256>>>(cols[g], vals[g], b2,
                                    out + (size_t)g * N_NODES * HID);
    }
}

// round 2
// speedup vs baseline: 1.0756x; 1.0756x over previous
#include <cuda_runtime.h>
#include <math.h>

#define N_NODES 100000
#define N_EDGES 1200000
#define HID 64
#define NTOT (2 * N_NODES)
#define NB2 196   // ceil(200000/1024)

typedef unsigned long long ull;

// ---------------- scratch (device globals, no allocation) ----------------
__device__ float g_H[2 * (size_t)N_NODES * HID];
__device__ float g_Z[2 * (size_t)N_NODES * HID];
__device__ int   g_rowptr[NTOT + 1];
__device__ int2  g_edge[2 * N_EDGES];    // sorted (col, val-bits) per dest row
__device__ int   g_cnt[NTOT];
__device__ int   g_bsums[NB2 + 1];

// ---------------- packed fp32 helpers ----------------
__device__ __forceinline__ void ffma2(ull& c, ull a, ull b) {
    asm("fma.rn.f32x2 %0, %1, %2, %0;" : "+l"(c) : "l"(a), "l"(b));
}
__device__ __forceinline__ ull pack2(float x, float y) {
    ull r;
    asm("mov.b64 %0, {%1, %2};" : "=l"(r) : "f"(x), "f"(y));
    return r;
}

// ---------------- CSR build (both graphs at once) ----------------
__global__ void zero_cnt_kernel() {
    int i = blockIdx.x * 256 + threadIdx.x;
    if (i < NTOT) g_cnt[i] = 0;
}

__global__ void edge_count_kernel(const int* __restrict__ rows1,
                                  const int* __restrict__ rows2) {
    int e = blockIdx.x * 256 + threadIdx.x;
    if (e < 2 * N_EDGES) {
        int g = e >= N_EDGES;
        int le = e - g * N_EDGES;
        int r = g ? rows2[le] : rows1[le];
        atomicAdd(&g_cnt[g * N_NODES + r], 1);
    }
}

__global__ void scan_reduce_kernel() {
    __shared__ int s[256];
    int t = threadIdx.x;
    int base = blockIdx.x * 1024 + t * 4;
    int v = 0;
#pragma unroll
    for (int i = 0; i < 4; i++) {
        int idx = base + i;
        if (idx < NTOT) v += g_cnt[idx];
    }
    s[t] = v;
    __syncthreads();
    for (int o = 128; o; o >>= 1) {
        if (t < o) s[t] += s[t + o];
        __syncthreads();
    }
    if (t == 0) g_bsums[blockIdx.x] = s[0];
}

__global__ void scan_bsums_kernel() {
    __shared__ int s[2][256];
    int t = threadIdx.x;
    int v = (t < NB2) ? g_bsums[t] : 0;
    int buf = 0;
    s[0][t] = v;
    __syncthreads();
    for (int o = 1; o < 256; o <<= 1) {
        int x = s[buf][t];
        if (t >= o) x += s[buf][t - o];
        s[buf ^ 1][t] = x;
        buf ^= 1;
        __syncthreads();
    }
    int inc = s[buf][t];
    if (t < NB2) g_bsums[t] = inc - v;   // exclusive
    if (t == 255) g_bsums[NB2] = inc;    // total
}

__global__ void scan_final_kernel() {
    __shared__ int s[2][256];
    int t = threadIdx.x;
    int base = blockIdx.x * 1024 + t * 4;
    int v[4];
#pragma unroll
    for (int i = 0; i < 4; i++)
        v[i] = (base + i < NTOT) ? g_cnt[base + i] : 0;
    int tot = v[0] + v[1] + v[2] + v[3];
    int buf = 0;
    s[0][t] = tot;
    __syncthreads();
    for (int o = 1; o < 256; o <<= 1) {
        int x = s[buf][t];
        if (t >= o) x += s[buf][t - o];
        s[buf ^ 1][t] = x;
        buf ^= 1;
        __syncthreads();
    }
    int run = s[buf][t] - tot + g_bsums[blockIdx.x];
#pragma unroll
    for (int i = 0; i < 4; i++) {
        if (base + i < NTOT) {
            g_rowptr[base + i] = run;
            g_cnt[base + i] = 0;          // fused re-zero for the scatter pass
        }
        run += v[i];
    }
    if (blockIdx.x == 0 && t == 0) g_rowptr[NTOT] = g_bsums[NB2];
}

__global__ void edge_scatter_kernel(const int* __restrict__ rows1,
                                    const int* __restrict__ cols1,
                                    const float* __restrict__ vals1,
                                    const int* __restrict__ rows2,
                                    const int* __restrict__ cols2,
                                    const float* __restrict__ vals2) {
    int e = blockIdx.x * 256 + threadIdx.x;
    if (e < 2 * N_EDGES) {
        int g = e >= N_EDGES;
        int le = e - g * N_EDGES;
        int r, c; float v;
        if (g) { r = rows2[le]; c = cols2[le]; v = vals2[le]; }
        else   { r = rows1[le]; c = cols1[le]; v = vals1[le]; }
        int key = g * N_NODES + r;
        int p = g_rowptr[key] + atomicAdd(&g_cnt[key], 1);
        g_edge[p] = make_int2(c, __float_as_int(v));
    }
}

// ---------------- GEMM: H[g] = A[g] @ B, packed-FFMA2 inner loop ----------------
// BM=64, BN=64, BK=16, 256 threads, 4 rows x 4 cols per thread.
__global__ __launch_bounds__(256) void gemm64_kernel(const float* __restrict__ X1,
                                                     const float* __restrict__ X2,
                                                     int use_z,
                                                     const float* __restrict__ B,
                                                     int K) {
    int g = blockIdx.y;
    const float* __restrict__ A =
        use_z ? (g_Z + (size_t)g * N_NODES * HID) : (g ? X2 : X1);
    float* __restrict__ Hout = g_H + (size_t)g * N_NODES * HID;

    __shared__ float As[16][68];   // [k][m], padded (stride 272B, 16B-aligned)
    __shared__ float Bs[16][64];   // [k][n]
    int tid = threadIdx.x;
    int tx = tid & 15, ty = tid >> 4;
    int row0 = blockIdx.x * 64;

    ull acc[4][2];
#pragma unroll
    for (int i = 0; i < 4; i++) { acc[i][0] = 0ull; acc[i][1] = 0ull; }

    for (int k0 = 0; k0 < K; k0 += 16) {
#pragma unroll
        for (int i = 0; i < 4; i++) {
            int idx = tid + i * 256;
            int m = idx >> 4, kk = idx & 15;
            int gr = row0 + m;
            As[kk][m] = (gr < N_NODES) ? __ldg(&A[(size_t)gr * K + k0 + kk]) : 0.f;
        }
#pragma unroll
        for (int i = 0; i < 4; i++) {
            int idx = tid + i * 256;
            int kk = idx >> 6, n = idx & 63;
            Bs[kk][n] = __ldg(&B[(k0 + kk) * 64 + n]);
        }
        __syncthreads();
#pragma unroll
        for (int kk = 0; kk < 16; kk++) {
            float4 a4 = *(const float4*)&As[kk][ty * 4];
            ulonglong2 bv = *(const ulonglong2*)&Bs[kk][tx * 4];
            ull ad;
            ad = pack2(a4.x, a4.x); ffma2(acc[0][0], ad, bv.x); ffma2(acc[0][1], ad, bv.y);
            ad = pack2(a4.y, a4.y); ffma2(acc[1][0], ad, bv.x); ffma2(acc[1][1], ad, bv.y);
            ad = pack2(a4.z, a4.z); ffma2(acc[2][0], ad, bv.x); ffma2(acc[2][1], ad, bv.y);
            ad = pack2(a4.w, a4.w); ffma2(acc[3][0], ad, bv.x); ffma2(acc[3][1], ad, bv.y);
        }
        __syncthreads();
    }
#pragma unroll
    for (int i = 0; i < 4; i++) {
        int row = row0 + ty * 4 + i;
        if (row < N_NODES) {
            ulonglong2 v; v.x = acc[i][0]; v.y = acc[i][1];
            *(ulonglong2*)&Hout[(size_t)row * 64 + tx * 4] = v;
        }
    }
}

// ---------------- SPMM (CSR gather, MLP=4 batches) + fused epilogue ----------------
__device__ __forceinline__ float warp_sum(float v) {
#pragma unroll
    for (int o = 16; o; o >>= 1) v += __shfl_xor_sync(0xffffffffu, v, o);
    return v;
}

// MODE 0: Z[g] = SELU(A@H + b) ; MODE 1: out[g] = rownorm(A@H + b)
template <int MODE>
__global__ __launch_bounds__(256) void spmm_kernel(const float* __restrict__ bias,
                                                   float* __restrict__ out_ext) {
    int g = blockIdx.y;
    int warp = threadIdx.x >> 5, lane = threadIdx.x & 31;
    int row = blockIdx.x * 8 + warp;
    if (row >= N_NODES) return;
    const float* __restrict__ H = g_H + (size_t)g * N_NODES * HID;
    int key = g * N_NODES + row;
    int s = g_rowptr[key], e = g_rowptr[key + 1];
    float ax = 0.f, ay = 0.f;
    int j = s;
    for (; j + 4 <= e; j += 4) {
        int2 e0 = g_edge[j], e1 = g_edge[j + 1], e2 = g_edge[j + 2], e3 = g_edge[j + 3];
        float2 h0 = *(const float2*)&H[(size_t)e0.x * 64 + lane * 2];
        float2 h1 = *(const float2*)&H[(size_t)e1.x * 64 + lane * 2];
        float2 h2 = *(const float2*)&H[(size_t)e2.x * 64 + lane * 2];
        float2 h3 = *(const float2*)&H[(size_t)e3.x * 64 + lane * 2];
        float v0 = __int_as_float(e0.y), v1 = __int_as_float(e1.y);
        float v2 = __int_as_float(e2.y), v3 = __int_as_float(e3.y);
        ax += v0 * h0.x + v1 * h1.x + v2 * h2.x + v3 * h3.x;
        ay += v0 * h0.y + v1 * h1.y + v2 * h2.y + v3 * h3.y;
    }
    for (; j < e; j++) {
        int2 ed = g_edge[j];
        float v = __int_as_float(ed.y);
        float2 h = *(const float2*)&H[(size_t)ed.x * 64 + lane * 2];
        ax += v * h.x;
        ay += v * h.y;
    }
    ax += __ldg(&bias[lane * 2]);
    ay += __ldg(&bias[lane * 2 + 1]);
    if (MODE == 0) {
        const float sc = 1.0507009873554805f, al = 1.6732632423543772f;
        ax = ax > 0.f ? sc * ax : sc * al * expm1f(ax);
        ay = ay > 0.f ? sc * ay : sc * al * expm1f(ay);
        float2 o = {ax, ay};
        *(float2*)&g_Z[((size_t)g * N_NODES + row) * HID + lane * 2] = o;
    } else {
        float ss = warp_sum(ax * ax + ay * ay);
        float inv = 1.f / fmaxf(sqrtf(ss), 1e-12f);
        float2 o = {ax * inv, ay * inv};
        *(float2*)&out_ext[((size_t)g * N_NODES + row) * HID + lane * 2] = o;
    }
}

// ---------------- launch ----------------
extern "C" void kernel_launch(void* const* d_in, const int* in_sizes, int n_in,
                              void* d_out, int out_size) {
    const float* X1 = (const float*)d_in[0];
    const float* X2 = (const float*)d_in[1];
    const int*   rows1 = (const int*)d_in[2];
    const int*   cols1 = (const int*)d_in[3];
    const float* vals1 = (const float*)d_in[4];
    const int*   rows2 = (const int*)d_in[5];
    const int*   cols2 = (const int*)d_in[6];
    const float* vals2 = (const float*)d_in[7];
    const float* W1 = (const float*)d_in[8];
    const float* b1 = (const float*)d_in[9];
    const float* W2 = (const float*)d_in[10];
    const float* b2 = (const float*)d_in[11];
    float* out = (float*)d_out;

    const int ZG = (NTOT + 255) / 256;          // 782
    const int EG = (2 * N_EDGES + 255) / 256;   // 9375
    dim3 GG((N_NODES + 63) / 64, 2);            // (1563, 2)
    dim3 SG((N_NODES + 7) / 8, 2);              // (12500, 2)

    // CSR build, both graphs in one pipeline
    zero_cnt_kernel<<<ZG, 256>>>();
    edge_count_kernel<<<EG, 256>>>(rows1, rows2);
    scan_reduce_kernel<<<NB2, 256>>>();
    scan_bsums_kernel<<<1, 256>>>();
    scan_final_kernel<<<NB2, 256>>>();          // also re-zeroes g_cnt
    edge_scatter_kernel<<<EG, 256>>>(rows1, cols1, vals1, rows2, cols2, vals2);

    // layer 1: H = X @ W1 ; Z = SELU(A@H + b1)
    gemm64_kernel<<<GG, 256>>>(X1, X2, 0, W1, 256);
    spmm_kernel<0><<<SG, 256>>>(b1, nullptr);

    // layer 2: H = Z @ W2 ; out = rownorm(A@H + b2)
    gemm64_kernel<<<GG, 256>>>(X1, X2, 1, W2, HID);
    spmm_kernel<1><<<SG, 256>>>(b2, out);
}

// round 4
// speedup vs baseline: 1.1779x; 1.0952x over previous
#include <cuda_runtime.h>
#include <math.h>

#define N_NODES 100000
#define N_EDGES 1200000
#define HID 64
#define NTOT (2 * N_NODES)
#define NB2 196   // ceil(200000/1024)

typedef unsigned long long ull;

// ---------------- scratch (device globals, no allocation) ----------------
__device__ float g_H[2 * (size_t)N_NODES * HID];
__device__ float g_Z[2 * (size_t)N_NODES * HID];
__device__ int   g_rowptr[NTOT + 1];
__device__ int2  g_edge[2 * N_EDGES];    // sorted (col, val-bits) per dest row
__device__ int   g_cnt[NTOT];
__device__ int   g_bsums[NB2 + 1];

// ---------------- packed fp32 helpers ----------------
__device__ __forceinline__ void ffma2(ull& c, ull a, ull b) {
    asm("fma.rn.f32x2 %0, %1, %2, %0;" : "+l"(c) : "l"(a), "l"(b));
}
__device__ __forceinline__ ull pack2(float x, float y) {
    ull r;
    asm("mov.b64 %0, {%1, %2};" : "=l"(r) : "f"(x), "f"(y));
    return r;
}

// ---------------- CSR build (both graphs at once) ----------------
__global__ void zero_cnt_kernel() {
    int i = blockIdx.x * 256 + threadIdx.x;
    if (i < NTOT) g_cnt[i] = 0;
}

__global__ void edge_count_kernel(const int* __restrict__ rows1,
                                  const int* __restrict__ rows2) {
    int e = blockIdx.x * 256 + threadIdx.x;
    if (e < 2 * N_EDGES) {
        int g = e >= N_EDGES;
        int le = e - g * N_EDGES;
        int r = g ? rows2[le] : rows1[le];
        atomicAdd(&g_cnt[g * N_NODES + r], 1);
    }
}

__global__ void scan_reduce_kernel() {
    __shared__ int s[256];
    int t = threadIdx.x;
    int base = blockIdx.x * 1024 + t * 4;
    int v = 0;
#pragma unroll
    for (int i = 0; i < 4; i++) {
        int idx = base + i;
        if (idx < NTOT) v += g_cnt[idx];
    }
    s[t] = v;
    __syncthreads();
    for (int o = 128; o; o >>= 1) {
        if (t < o) s[t] += s[t + o];
        __syncthreads();
    }
    if (t == 0) g_bsums[blockIdx.x] = s[0];
}

__global__ void scan_bsums_kernel() {
    __shared__ int s[2][256];
    int t = threadIdx.x;
    int v = (t < NB2) ? g_bsums[t] : 0;
    int buf = 0;
    s[0][t] = v;
    __syncthreads();
    for (int o = 1; o < 256; o <<= 1) {
        int x = s[buf][t];
        if (t >= o) x += s[buf][t - o];
        s[buf ^ 1][t] = x;
        buf ^= 1;
        __syncthreads();
    }
    int inc = s[buf][t];
    if (t < NB2) g_bsums[t] = inc - v;   // exclusive
    if (t == 255) g_bsums[NB2] = inc;    // total
}

__global__ void scan_final_kernel() {
    __shared__ int s[2][256];
    int t = threadIdx.x;
    int base = blockIdx.x * 1024 + t * 4;
    int v[4];
#pragma unroll
    for (int i = 0; i < 4; i++)
        v[i] = (base + i < NTOT) ? g_cnt[base + i] : 0;
    int tot = v[0] + v[1] + v[2] + v[3];
    int buf = 0;
    s[0][t] = tot;
    __syncthreads();
    for (int o = 1; o < 256; o <<= 1) {
        int x = s[buf][t];
        if (t >= o) x += s[buf][t - o];
        s[buf ^ 1][t] = x;
        buf ^= 1;
        __syncthreads();
    }
    int run = s[buf][t] - tot + g_bsums[blockIdx.x];
#pragma unroll
    for (int i = 0; i < 4; i++) {
        if (base + i < NTOT) {
            g_rowptr[base + i] = run;
            g_cnt[base + i] = 0;          // fused re-zero for the scatter pass
        }
        run += v[i];
    }
    if (blockIdx.x == 0 && t == 0) g_rowptr[NTOT] = g_bsums[NB2];
}

__global__ void edge_scatter_kernel(const int* __restrict__ rows1,
                                    const int* __restrict__ cols1,
                                    const float* __restrict__ vals1,
                                    const int* __restrict__ rows2,
                                    const int* __restrict__ cols2,
                                    const float* __restrict__ vals2) {
    int e = blockIdx.x * 256 + threadIdx.x;
    if (e < 2 * N_EDGES) {
        int g = e >= N_EDGES;
        int le = e - g * N_EDGES;
        int r, c; float v;
        if (g) { r = rows2[le]; c = cols2[le]; v = vals2[le]; }
        else   { r = rows1[le]; c = cols1[le]; v = vals1[le]; }
        int key = g * N_NODES + r;
        int p = g_rowptr[key] + atomicAdd(&g_cnt[key], 1);
        g_edge[p] = make_int2(c, __float_as_int(v));
    }
}

// ---------------- GEMM: H[g] = A[g] @ B[K x 64] ----------------
// BM=128, BN=64, BK=16, 256 threads, 8 rows x 4 cols per thread, FFMA2 inner,
// register prefetch of the next gmem tile.
__global__ __launch_bounds__(256) void gemm128_kernel(const float* __restrict__ X1,
                                                      const float* __restrict__ X2,
                                                      int use_z,
                                                      const float* __restrict__ B,
                                                      int K) {
    int g = blockIdx.y;
    const float* __restrict__ A =
        use_z ? (g_Z + (size_t)g * N_NODES * HID) : (g ? X2 : X1);
    float* __restrict__ Hout = g_H + (size_t)g * N_NODES * HID;

    __shared__ float As[16][132];   // [k][m], row stride 528B (16B aligned)
    __shared__ float Bs[16][64];    // [k][n]
    int tid = threadIdx.x;
    int tx = tid & 15, ty = tid >> 4;
    int row0 = blockIdx.x * 128;

    // gmem load assignment
    int am = tid >> 1;            // 0..127: A row within tile
    int af = (tid & 1) * 8;       // k offset within BK: 0 or 8 (two float4s)
    int bk = tid >> 4;            // 0..15
    int bn = (tid & 15) * 4;
    int arow = row0 + am;
    bool a_ok = arow < N_NODES;
    const float* Abase = A + (size_t)arow * K;

    ull acc[8][2];
#pragma unroll
    for (int i = 0; i < 8; i++) { acc[i][0] = 0ull; acc[i][1] = 0ull; }

    float4 pa0, pa1, pb;
    // prologue: load tile 0
    pa0 = a_ok ? *(const float4*)&Abase[af]     : make_float4(0, 0, 0, 0);
    pa1 = a_ok ? *(const float4*)&Abase[af + 4] : make_float4(0, 0, 0, 0);
    pb  = *(const float4*)&B[bk * 64 + bn];

    for (int k0 = 0; k0 < K; k0 += 16) {
        // commit prefetched tile to smem
        As[af + 0][am] = pa0.x; As[af + 1][am] = pa0.y;
        As[af + 2][am] = pa0.z; As[af + 3][am] = pa0.w;
        As[af + 4][am] = pa1.x; As[af + 5][am] = pa1.y;
        As[af + 6][am] = pa1.z; As[af + 7][am] = pa1.w;
        *(float4*)&Bs[bk][bn] = pb;
        __syncthreads();

        // prefetch next tile (overlaps compute)
        if (k0 + 16 < K) {
            pa0 = a_ok ? *(const float4*)&Abase[k0 + 16 + af]     : make_float4(0, 0, 0, 0);
            pa1 = a_ok ? *(const float4*)&Abase[k0 + 16 + af + 4] : make_float4(0, 0, 0, 0);
            pb  = *(const float4*)&B[(k0 + 16 + bk) * 64 + bn];
        }

#pragma unroll
        for (int kk = 0; kk < 16; kk++) {
            float4 a4 = *(const float4*)&As[kk][ty * 8];
            float4 a8 = *(const float4*)&As[kk][ty * 8 + 4];
            ulonglong2 bv = *(const ulonglong2*)&Bs[kk][tx * 4];
            ull ad;
            ad = pack2(a4.x, a4.x); ffma2(acc[0][0], ad, bv.x); ffma2(acc[0][1], ad, bv.y);
            ad = pack2(a4.y, a4.y); ffma2(acc[1][0], ad, bv.x); ffma2(acc[1][1], ad, bv.y);
            ad = pack2(a4.z, a4.z); ffma2(acc[2][0], ad, bv.x); ffma2(acc[2][1], ad, bv.y);
            ad = pack2(a4.w, a4.w); ffma2(acc[3][0], ad, bv.x); ffma2(acc[3][1], ad, bv.y);
            ad = pack2(a8.x, a8.x); ffma2(acc[4][0], ad, bv.x); ffma2(acc[4][1], ad, bv.y);
            ad = pack2(a8.y, a8.y); ffma2(acc[5][0], ad, bv.x); ffma2(acc[5][1], ad, bv.y);
            ad = pack2(a8.z, a8.z); ffma2(acc[6][0], ad, bv.x); ffma2(acc[6][1], ad, bv.y);
            ad = pack2(a8.w, a8.w); ffma2(acc[7][0], ad, bv.x); ffma2(acc[7][1], ad, bv.y);
        }
        __syncthreads();
    }
#pragma unroll
    for (int i = 0; i < 8; i++) {
        int row = row0 + ty * 8 + i;
        if (row < N_NODES) {
            ulonglong2 v; v.x = acc[i][0]; v.y = acc[i][1];
            *(ulonglong2*)&Hout[(size_t)row * 64 + tx * 4] = v;
        }
    }
}

// ---------------- SPMM (CSR gather, 8+4 batches) + fused epilogue ----------------
__device__ __forceinline__ float warp_sum(float v) {
#pragma unroll
    for (int o = 16; o; o >>= 1) v += __shfl_xor_sync(0xffffffffu, v, o);
    return v;
}

// MODE 0: Z[g] = SELU(A@H + b) ; MODE 1: out[g] = rownorm(A@H + b)
template <int MODE>
__global__ __launch_bounds__(256) void spmm_kernel(const float* __restrict__ bias,
                                                   float* __restrict__ out_ext) {
    int g = blockIdx.y;
    int warp = threadIdx.x >> 5, lane = threadIdx.x & 31;
    int row = blockIdx.x * 8 + warp;
    if (row >= N_NODES) return;
    const float* __restrict__ H = g_H + (size_t)g * N_NODES * HID;
    int key = g * N_NODES + row;
    int s = g_rowptr[key], e = g_rowptr[key + 1];
    float bx = __ldg(&bias[lane * 2]);
    float by = __ldg(&bias[lane * 2 + 1]);
    float ax = 0.f, ay = 0.f;
    int j = s;
    for (; j + 8 <= e; j += 8) {
        int2 ed[8];
#pragma unroll
        for (int i = 0; i < 8; i++) ed[i] = g_edge[j + i];
        float2 h[8];
#pragma unroll
        for (int i = 0; i < 8; i++)
            h[i] = *(const float2*)&H[(size_t)ed[i].x * 64 + lane * 2];
#pragma unroll
        for (int i = 0; i < 8; i++) {
            float v = __int_as_float(ed[i].y);
            ax += v * h[i].x;
            ay += v * h[i].y;
        }
    }
    if (j + 4 <= e) {
        int2 ed[4];
#pragma unroll
        for (int i = 0; i < 4; i++) ed[i] = g_edge[j + i];
        float2 h[4];
#pragma unroll
        for (int i = 0; i < 4; i++)
            h[i] = *(const float2*)&H[(size_t)ed[i].x * 64 + lane * 2];
#pragma unroll
        for (int i = 0; i < 4; i++) {
            float v = __int_as_float(ed[i].y);
            ax += v * h[i].x;
            ay += v * h[i].y;
        }
        j += 4;
    }
    for (; j < e; j++) {
        int2 ed = g_edge[j];
        float v = __int_as_float(ed.y);
        float2 h = *(const float2*)&H[(size_t)ed.x * 64 + lane * 2];
        ax += v * h.x;
        ay += v * h.y;
    }
    ax += bx;
    ay += by;
    if (MODE == 0) {
        const float sc = 1.0507009873554805f, al = 1.6732632423543772f;
        ax = ax > 0.f ? sc * ax : sc * al * expm1f(ax);
        ay = ay > 0.f ? sc * ay : sc * al * expm1f(ay);
        float2 o = {ax, ay};
        *(float2*)&g_Z[((size_t)g * N_NODES + row) * HID + lane * 2] = o;
    } else {
        float ss = warp_sum(ax * ax + ay * ay);
        float inv = 1.f / fmaxf(sqrtf(ss), 1e-12f);
        float2 o = {ax * inv, ay * inv};
        *(float2*)&out_ext[((size_t)g * N_NODES + row) * HID + lane * 2] = o;
    }
}

// ---------------- launch ----------------
extern "C" void kernel_launch(void* const* d_in, const int* in_sizes, int n_in,
                              void* d_out, int out_size) {
    const float* X1 = (const float*)d_in[0];
    const float* X2 = (const float*)d_in[1];
    const int*   rows1 = (const int*)d_in[2];
    const int*   cols1 = (const int*)d_in[3];
    const float* vals1 = (const float*)d_in[4];
    const int*   rows2 = (const int*)d_in[5];
    const int*   cols2 = (const int*)d_in[6];
    const float* vals2 = (const float*)d_in[7];
    const float* W1 = (const float*)d_in[8];
    const float* b1 = (const float*)d_in[9];
    const float* W2 = (const float*)d_in[10];
    const float* b2 = (const float*)d_in[11];
    float* out = (float*)d_out;

    const int ZG = (NTOT + 255) / 256;          // 782
    const int EG = (2 * N_EDGES + 255) / 256;   // 9375
    dim3 GG((N_NODES + 127) / 128, 2);          // (782, 2)
    dim3 SG((N_NODES + 7) / 8, 2);              // (12500, 2)

    // CSR build interleaved with GEMM layer 1 (gemm placed as launch #3 so the
    // fixed ncu sample window lands on it).
    zero_cnt_kernel<<<ZG, 256>>>();
    edge_count_kernel<<<EG, 256>>>(rows1, rows2);
    scan_reduce_kernel<<<NB2, 256>>>();
    gemm128_kernel<<<GG, 256>>>(X1, X2, 0, W1, 256);   // H = X @ W1 (CSR-independent)
    scan_bsums_kernel<<<1, 256>>>();
    scan_final_kernel<<<NB2, 256>>>();                 // also re-zeroes g_cnt
    edge_scatter_kernel<<<EG, 256>>>(rows1, cols1, vals1, rows2, cols2, vals2);

    // layer 1 aggregate: Z = SELU(A@H + b1)
    spmm_kernel<0><<<SG, 256>>>(b1, nullptr);

    // layer 2: H = Z @ W2 ; out = rownorm(A@H + b2)
    gemm128_kernel<<<GG, 256>>>(X1, X2, 1, W2, HID);
    spmm_kernel<1><<<SG, 256>>>(b2, out);
}